// round 16
// baseline (speedup 1.0000x reference)
#include <cuda_runtime.h>
#include <cstdint>
#include <math.h>

#define T_SEQ   4096
#define NNODES  64
#define FPL     8
#define OBS_DIM 512
#define HID     64
#define GATES   256
#define CHUNK   32
#define FULLMASK 0xffffffffu

// scratch (static device allocations — allowed)
__device__ int   g_hbar_i[T_SEQ * HID];        // 1 MB: sum_n round(h*2^22)
__device__ float g_Wg_t[HID * GATES];
__device__ float g_Wm_t[GATES * HID];
__device__ float g_Ws_t[GATES * HID];

typedef unsigned long long ull;
typedef unsigned int u32;

__device__ __forceinline__ void ffma2(ull& d, const ull a, const ull b) {
    asm("fma.rn.f32x2 %0, %1, %2, %0;" : "+l"(d) : "l"(a), "l"(b));
}
__device__ __forceinline__ ull addf2(ull a, ull b) {
    ull r; asm("add.rn.f32x2 %0, %1, %2;" : "=l"(r) : "l"(a), "l"(b)); return r;
}
__device__ __forceinline__ float2 unpack2(ull v) {
    float2 f; asm("mov.b64 {%0, %1}, %2;" : "=f"(f.x), "=f"(f.y) : "l"(v)); return f;
}
__device__ __forceinline__ ull pack2(float lo, float hi) {
    ull v; asm("mov.b64 %0, {%1, %2};" : "=l"(v) : "f"(lo), "f"(hi)); return v;
}
__device__ __forceinline__ float tanh_mufu(float x) {
    float r; asm("tanh.approx.f32 %0, %1;" : "=f"(r) : "f"(x)); return r;
}
__device__ __forceinline__ u32 smem_u32(const void* p) {
    u32 a;
    asm("{ .reg .u64 t; cvta.to.shared.u64 t, %1; cvt.u32.u64 %0, t; }"
        : "=r"(a) : "l"(p));
    return a;
}

// ---------------------------------------------------------------------------
// Kernel 1: LSTM (CTAs 0..63, one node each) + weight transposes for the
// head (CTAs 64..127, finish in microseconds and exit, freeing their SMs).
//
// LSTM body = round-8 winner: 256 threads, thread -> gate row
// r = (tid&3)*64 + (tid>>2); MUFU.TANH activations with pre-scaled weights
// (sigma(z) = 0.5 + 0.5*tanh(z/2)); quad shuffle gather; no BSSY/BSYNC in
// the step body. h history kept in smem (hh[s+1]).
// NEW: per-chunk epilogue quantizes h to int (round(h*2^22)) and
// RED.ADD.s32-accumulates the cross-node sum into g_hbar_i — exactly
// associative integer math -> deterministic; the 64 MB g_hs tensor is gone.
// ---------------------------------------------------------------------------
__global__ void __launch_bounds__(256, 1)
lstm_kernel(const float* __restrict__ x,
            const float* __restrict__ W_ih,
            const float* __restrict__ W_hh,
            const float* __restrict__ b_ih,
            const float* __restrict__ b_hh,
            const float* __restrict__ Wg,
            const float* __restrict__ Wm,
            const float* __restrict__ Ws,
            float* __restrict__ out)
{
    // ---- transpose helper CTAs ----
    if (blockIdx.x >= NNODES) {
        int i = (blockIdx.x - NNODES) * 256 + threadIdx.x;
        int j = i >> 6, k = i & 63;
        g_Wg_t[k * GATES + j] = Wg[i];
        int a = i >> 8, jj = i & 255;
        g_Wm_t[jj * HID + a] = Wm[i];
        g_Ws_t[jj * HID + a] = Ws[i];
        return;
    }

    // ---- LSTM CTA ----
    const int n    = blockIdx.x;
    const int tid  = threadIdx.x;
    const int k    = tid >> 2;
    const int gate = tid & 3;
    const int r    = gate * HID + k;
    const unsigned lane = tid & 31u;
    const unsigned lb   = lane & ~3u;

    const bool  is_g = (gate == 2);
    const float m    = is_g ? 1.0f : 0.5f;   // tanh(z) vs 0.5+0.5*tanh(z/2)
    const float Aact = is_g ? 1.0f : 0.5f;
    const float Bact = is_g ? 0.0f : 0.5f;

    __shared__ __align__(16) float hh[CHUNK + 1][HID];   // 8.25 KB history
    __shared__ __align__(16) float xs[2][CHUNK][FPL];    // 2 KB

    // weights in registers, pre-scaled by m, packed f32x2
    ull whh[32];
    {
        const float* wrow = W_hh + r * HID;
#pragma unroll
        for (int i = 0; i < 32; i++)
            whh[i] = pack2(wrow[2*i] * m, wrow[2*i+1] * m);
    }
    ull wih[4];
    {
        const float* wrow = W_ih + r * FPL;
#pragma unroll
        for (int i = 0; i < 4; i++)
            wih[i] = pack2(wrow[2*i] * m, wrow[2*i+1] * m);
    }
    const float bsum = (b_ih[r] + b_hh[r]) * m;

    const u32 hh_base = smem_u32(hh);
    float c_reg = 0.0f;
    if (tid < HID) hh[0][tid] = 0.0f;

    // prologue: stage x chunk 0
    {
        int s = tid >> 3, j = tid & 7;
        xs[0][s][j] = x[s * OBS_DIM + n * FPL + j];
    }
    __syncthreads();

    for (int b = 0; b < T_SEQ / CHUNK; b++) {
        // prefetch next x chunk into a register (hidden over 32 steps)
        float xpref = 0.0f;
        {
            int tn = (b + 1) * CHUNK + (tid >> 3);
            if (tn < T_SEQ) xpref = x[tn * OBS_DIM + n * FPL + (tid & 7)];
        }
#pragma unroll 4
        for (int s = 0; s < CHUNK; s++) {
            // acc = m*(bias + W_ih·x + W_hh·h)   (8 packed accumulators)
            ull a0 = pack2(bsum, 0.0f), a1 = 0, a2 = 0, a3 = 0;
            ull a4 = 0, a5 = 0, a6 = 0, a7 = 0;
            {
                const ulonglong2* xp = (const ulonglong2*)xs[b & 1][s];
                ulonglong2 xv0 = xp[0], xv1 = xp[1];
                ffma2(a0, wih[0], xv0.x);
                ffma2(a2, wih[1], xv0.y);
                ffma2(a4, wih[2], xv1.x);
                ffma2(a6, wih[3], xv1.y);
            }
            const ulonglong2* hp = (const ulonglong2*)hh[s];
#pragma unroll
            for (int mm = 0; mm < 4; mm++) {
                ulonglong2 hv0 = hp[4*mm + 0], hv1 = hp[4*mm + 1];
                ulonglong2 hv2 = hp[4*mm + 2], hv3 = hp[4*mm + 3];
                ffma2(a0, whh[8*mm+0], hv0.x);
                ffma2(a1, whh[8*mm+1], hv0.y);
                ffma2(a2, whh[8*mm+2], hv1.x);
                ffma2(a3, whh[8*mm+3], hv1.y);
                ffma2(a4, whh[8*mm+4], hv2.x);
                ffma2(a5, whh[8*mm+5], hv2.y);
                ffma2(a6, whh[8*mm+6], hv3.x);
                ffma2(a7, whh[8*mm+7], hv3.y);
            }
            // packed reduction tree
            ull b0 = addf2(a0, a1), b1 = addf2(a2, a3);
            ull b2 = addf2(a4, a5), b3 = addf2(a6, a7);
            float2 f = unpack2(addf2(addf2(b0, b1), addf2(b2, b3)));
            const float accv = f.x + f.y;

            // activation: v = A*tanh(z) + B  (MUFU.TANH, branch-free)
            const float v = fmaf(tanh_mufu(accv), Aact, Bact);

            // gather i,f,g,o within the quad (independent shuffles)
            const float vi = __shfl_sync(FULLMASK, v, lb);
            const float vf = __shfl_sync(FULLMASK, v, lb | 1);
            const float vg = __shfl_sync(FULLMASK, v, lb | 2);
            const float vo = __shfl_sync(FULLMASK, v, lb | 3);

            // ALL lanes compute c/h (identical within the quad) — no branch
            c_reg = vf * c_reg + vi * vg;
            const float h = vo * tanh_mufu(c_reg);

            // predicated smem-history store (no BSSY/BSYNC): gate==0 commits
            {
                const u32 sts_addr = hh_base + (u32)(((s + 1) * HID + k) * 4);
                asm volatile(
                    "{ .reg .pred p; setp.eq.s32 p, %0, 0;\n\t"
                    "@p st.shared.f32 [%1], %2; }"
                    :: "r"(gate), "r"(sts_addr), "f"(h)
                    : "memory");
            }

            // stage next x chunk mid-way (write-only buffer this chunk)
            if (s == 20) xs[(b + 1) & 1][tid >> 3][tid & 7] = xpref;
            __syncthreads();
        }

        // carry value read first (ordered by last step's barrier)
        float hlast = (tid < HID) ? hh[CHUNK][tid] : 0.0f;

        // quantize + integer-atomic accumulate cross-node sum:
        // g_hbar_i[t][k] += round(h[t][n][k] * 2^22)  (exact int add ->
        // deterministic regardless of CTA ordering)
        {
            const int row = tid >> 3;              // 0..31 (t_local)
            const int c0  = (tid & 7) * 8;         // 8 consecutive k
            int* dst = g_hbar_i + (b * CHUNK + row) * HID + c0;
            const float* src = hh[row + 1] + c0;
#pragma unroll
            for (int i = 0; i < 8; i++) {
                int q = __float2int_rn(src[i] * 4194304.0f);   // 2^22
                atomicAdd(dst + i, q);
            }
        }
        __syncthreads();                            // epilogue reads done
        if (tid < HID) hh[0][tid] = hlast;          // carry into next chunk
        __syncthreads();                            // hh[0] visible to all
    }

    // hn / cn (final h is in hh[0] after the last carry)
    if (gate == 0) {
        const int base = 2 * T_SEQ * NNODES;
        out[base + n * HID + k] = hh[0][k];
        out[base + NNODES * HID + n * HID + k] = c_reg;
    }
}

// ---------------------------------------------------------------------------
// Kernel 2: warp-autonomous head. 512 CTAs x 8 warps; one warp per timestep.
// Phase 1 is now two L2-resident int loads per lane (g_hbar_i, 1 MB) —
// the 64 MB DRAM-latency phase is gone. Phases 2/3: L1-resident GEMVs.
// GAT collapses to identity-attention; mean-pool commutes with W_gat.
// ---------------------------------------------------------------------------
__global__ void __launch_bounds__(256, 4)
head_kernel(const float* __restrict__ b_gat,
            const float* __restrict__ b_mean,
            const float* __restrict__ b_std,
            float* __restrict__ out)
{
    const int w    = threadIdx.x >> 5;
    const int lane = threadIdx.x & 31;
    const int t    = blockIdx.x * 8 + w;

    __shared__ __align__(16) float hb[8][HID];
    __shared__ __align__(16) float gs[8][GATES];

    // Phase 1: hbar[k] = S[t][k] * 2^-22 / 64 = S * 2^-28
    {
        const int* p = g_hbar_i + t * HID;
        hb[w][lane]      = (float)p[lane]      * 3.725290298461914e-09f;
        hb[w][32 + lane] = (float)p[32 + lane] * 3.725290298461914e-09f;
    }
    __syncwarp();

    // Phase 2: g[j] = relu(W_gat[j,:]·hbar + b_gat[j]), 8 outputs per lane
#pragma unroll
    for (int i = 0; i < 8; i++) {
        const int j = i * 32 + lane;
        float acc = b_gat[j];
#pragma unroll 8
        for (int k = 0; k < HID; k++)
            acc += g_Wg_t[k * GATES + j] * hb[w][k];
        gs[w][j] = fmaxf(acc, 0.0f);
    }
    __syncwarp();

    // Phase 3: mean / std heads, 2 outputs each per lane
#pragma unroll
    for (int i = 0; i < 2; i++) {
        const int a = i * 32 + lane;
        float am = b_mean[a], as = b_std[a];
#pragma unroll 8
        for (int j = 0; j < GATES; j++) {
            const float gv = gs[w][j];
            am += g_Wm_t[j * HID + a] * gv;
            as += g_Ws_t[j * HID + a] * gv;
        }
        out[t * NNODES + a] = am;
        float sp = (as > 20.0f) ? as : log1pf(__expf(as));
        out[T_SEQ * NNODES + t * NNODES + a] = fminf(fmaxf(sp, 0.001f), 10.0f);
    }
}

// ---------------------------------------------------------------------------
// launch — memset (accumulator zero) + two kernels, all stream-ordered
// ---------------------------------------------------------------------------
extern "C" void kernel_launch(void* const* d_in, const int* in_sizes, int n_in,
                              void* d_out, int out_size)
{
    const float* x      = (const float*)d_in[0];
    const float* W_ih   = (const float*)d_in[1];
    const float* W_hh   = (const float*)d_in[2];
    const float* b_ih   = (const float*)d_in[3];
    const float* b_hh   = (const float*)d_in[4];
    const float* W_gat  = (const float*)d_in[5];
    // d_in[6], d_in[7] (att_src/att_dst) provably unused: identity adjacency
    // -> softmax over a single unmasked element == 1 for any logits.
    const float* b_gat  = (const float*)d_in[8];
    const float* W_mean = (const float*)d_in[9];
    const float* b_mean = (const float*)d_in[10];
    const float* W_std  = (const float*)d_in[11];
    const float* b_std  = (const float*)d_in[12];
    float* out = (float*)d_out;

    // zero the integer hbar accumulator (graph-capturable, no allocation)
    void* hbar_ptr = nullptr;
    cudaGetSymbolAddress(&hbar_ptr, g_hbar_i);
    cudaMemsetAsync(hbar_ptr, 0, T_SEQ * HID * sizeof(int), 0);

    lstm_kernel<<<NNODES + 64, 256>>>(x, W_ih, W_hh, b_ih, b_hh,
                                      W_gat, W_mean, W_std, out);
    head_kernel<<<T_SEQ / 8, 256>>>(b_gat, b_mean, b_std, out);
}

// round 17
// speedup vs baseline: 1.1396x; 1.1396x over previous
#include <cuda_runtime.h>
#include <cstdint>
#include <math.h>

#define T_SEQ   4096
#define NNODES  64
#define FPL     8
#define OBS_DIM 512
#define HID     64
#define GATES   256
#define CHUNK   32
#define TB      16          // timesteps per head CTA
#define FULLMASK 0xffffffffu

// scratch (static device allocations — allowed)
__device__ float g_hs[T_SEQ * NNODES * HID];   // 64 MB: h[t][n][k]
__device__ float g_Wg_t[HID * GATES];
__device__ float g_Wm_t[GATES * HID];
__device__ float g_Ws_t[GATES * HID];

typedef unsigned long long ull;
typedef unsigned int u32;

__device__ __forceinline__ void ffma2(ull& d, const ull a, const ull b) {
    asm("fma.rn.f32x2 %0, %1, %2, %0;" : "+l"(d) : "l"(a), "l"(b));
}
__device__ __forceinline__ ull addf2(ull a, ull b) {
    ull r; asm("add.rn.f32x2 %0, %1, %2;" : "=l"(r) : "l"(a), "l"(b)); return r;
}
__device__ __forceinline__ float2 unpack2(ull v) {
    float2 f; asm("mov.b64 {%0, %1}, %2;" : "=f"(f.x), "=f"(f.y) : "l"(v)); return f;
}
__device__ __forceinline__ ull pack2(float lo, float hi) {
    ull v; asm("mov.b64 %0, {%1, %2};" : "=l"(v) : "f"(lo), "f"(hi)); return v;
}
__device__ __forceinline__ float tanh_mufu(float x) {
    float r; asm("tanh.approx.f32 %0, %1;" : "=f"(r) : "f"(x)); return r;
}
__device__ __forceinline__ u32 smem_u32(const void* p) {
    u32 a;
    asm("{ .reg .u64 t; cvta.to.shared.u64 t, %1; cvt.u32.u64 %0, t; }"
        : "=r"(a) : "l"(p));
    return a;
}

// ---------------------------------------------------------------------------
// Kernel 1: LSTM (CTAs 0..63, one node each) + weight transposes for the
// head (CTAs 64..127, finish in microseconds and exit, freeing their SMs).
// Body = R13 proven best (~1043us): MUFU.TANH activations with pre-scaled
// weights, quad shuffle gather, predicated smem-history store, per-chunk
// coalesced STG.128 dump of h to g_hs. No atomics anywhere.
// ---------------------------------------------------------------------------
__global__ void __launch_bounds__(256, 1)
lstm_kernel(const float* __restrict__ x,
            const float* __restrict__ W_ih,
            const float* __restrict__ W_hh,
            const float* __restrict__ b_ih,
            const float* __restrict__ b_hh,
            const float* __restrict__ Wg,
            const float* __restrict__ Wm,
            const float* __restrict__ Ws,
            float* __restrict__ out)
{
    // ---- transpose helper CTAs ----
    if (blockIdx.x >= NNODES) {
        int i = (blockIdx.x - NNODES) * 256 + threadIdx.x;
        int j = i >> 6, k = i & 63;
        g_Wg_t[k * GATES + j] = Wg[i];
        int a = i >> 8, jj = i & 255;
        g_Wm_t[jj * HID + a] = Wm[i];
        g_Ws_t[jj * HID + a] = Ws[i];
        return;
    }

    // ---- LSTM CTA ----
    const int n    = blockIdx.x;
    const int tid  = threadIdx.x;
    const int k    = tid >> 2;
    const int gate = tid & 3;
    const int r    = gate * HID + k;
    const unsigned lane = tid & 31u;
    const unsigned lb   = lane & ~3u;

    const bool  is_g = (gate == 2);
    const float m    = is_g ? 1.0f : 0.5f;   // tanh(z) vs 0.5+0.5*tanh(z/2)
    const float Aact = is_g ? 1.0f : 0.5f;
    const float Bact = is_g ? 0.0f : 0.5f;

    __shared__ __align__(16) float hh[CHUNK + 1][HID];   // 8.25 KB history
    __shared__ __align__(16) float xs[2][CHUNK][FPL];    // 2 KB

    // weights in registers, pre-scaled by m, packed f32x2
    ull whh[32];
    {
        const float* wrow = W_hh + r * HID;
#pragma unroll
        for (int i = 0; i < 32; i++)
            whh[i] = pack2(wrow[2*i] * m, wrow[2*i+1] * m);
    }
    ull wih[4];
    {
        const float* wrow = W_ih + r * FPL;
#pragma unroll
        for (int i = 0; i < 4; i++)
            wih[i] = pack2(wrow[2*i] * m, wrow[2*i+1] * m);
    }
    const float bsum = (b_ih[r] + b_hh[r]) * m;

    const u32 hh_base = smem_u32(hh);
    float c_reg = 0.0f;
    if (tid < HID) hh[0][tid] = 0.0f;

    // prologue: stage x chunk 0
    {
        int s = tid >> 3, j = tid & 7;
        xs[0][s][j] = x[s * OBS_DIM + n * FPL + j];
    }
    __syncthreads();

    for (int b = 0; b < T_SEQ / CHUNK; b++) {
        // prefetch next x chunk into a register (hidden over 32 steps)
        float xpref = 0.0f;
        {
            int tn = (b + 1) * CHUNK + (tid >> 3);
            if (tn < T_SEQ) xpref = x[tn * OBS_DIM + n * FPL + (tid & 7)];
        }
#pragma unroll 4
        for (int s = 0; s < CHUNK; s++) {
            // acc = m*(bias + W_ih·x + W_hh·h)   (8 packed accumulators)
            ull a0 = pack2(bsum, 0.0f), a1 = 0, a2 = 0, a3 = 0;
            ull a4 = 0, a5 = 0, a6 = 0, a7 = 0;
            {
                const ulonglong2* xp = (const ulonglong2*)xs[b & 1][s];
                ulonglong2 xv0 = xp[0], xv1 = xp[1];
                ffma2(a0, wih[0], xv0.x);
                ffma2(a2, wih[1], xv0.y);
                ffma2(a4, wih[2], xv1.x);
                ffma2(a6, wih[3], xv1.y);
            }
            const ulonglong2* hp = (const ulonglong2*)hh[s];
#pragma unroll
            for (int mm = 0; mm < 4; mm++) {
                ulonglong2 hv0 = hp[4*mm + 0], hv1 = hp[4*mm + 1];
                ulonglong2 hv2 = hp[4*mm + 2], hv3 = hp[4*mm + 3];
                ffma2(a0, whh[8*mm+0], hv0.x);
                ffma2(a1, whh[8*mm+1], hv0.y);
                ffma2(a2, whh[8*mm+2], hv1.x);
                ffma2(a3, whh[8*mm+3], hv1.y);
                ffma2(a4, whh[8*mm+4], hv2.x);
                ffma2(a5, whh[8*mm+5], hv2.y);
                ffma2(a6, whh[8*mm+6], hv3.x);
                ffma2(a7, whh[8*mm+7], hv3.y);
            }
            // packed reduction tree
            ull b0 = addf2(a0, a1), b1 = addf2(a2, a3);
            ull b2 = addf2(a4, a5), b3 = addf2(a6, a7);
            float2 f = unpack2(addf2(addf2(b0, b1), addf2(b2, b3)));
            const float accv = f.x + f.y;

            // activation: v = A*tanh(z) + B  (MUFU.TANH, branch-free)
            const float v = fmaf(tanh_mufu(accv), Aact, Bact);

            // gather i,f,g,o within the quad (independent shuffles)
            const float vi = __shfl_sync(FULLMASK, v, lb);
            const float vf = __shfl_sync(FULLMASK, v, lb | 1);
            const float vg = __shfl_sync(FULLMASK, v, lb | 2);
            const float vo = __shfl_sync(FULLMASK, v, lb | 3);

            // ALL lanes compute c/h (identical within the quad) — no branch
            c_reg = vf * c_reg + vi * vg;
            const float h = vo * tanh_mufu(c_reg);

            // predicated smem-history store (no BSSY/BSYNC): gate==0 commits
            {
                const u32 sts_addr = hh_base + (u32)(((s + 1) * HID + k) * 4);
                asm volatile(
                    "{ .reg .pred p; setp.eq.s32 p, %0, 0;\n\t"
                    "@p st.shared.f32 [%1], %2; }"
                    :: "r"(gate), "r"(sts_addr), "f"(h)
                    : "memory");
            }

            // stage next x chunk mid-way (write-only buffer this chunk)
            if (s == 20) xs[(b + 1) & 1][tid >> 3][tid & 7] = xpref;
            __syncthreads();
        }

        // carry value read first (ordered by last step's barrier)
        float hlast = (tid < HID) ? hh[CHUNK][tid] : 0.0f;

        // coalesced dump of hh[1..32] -> g_hs rows b*32 .. b*32+31
        {
            const int row = tid >> 3;              // 0..31
            const int c0  = (tid & 7) * 8;         // 8 floats per thread
            const float4* src = (const float4*)(hh[row + 1] + c0);
            float4 v0 = src[0], v1 = src[1];
            float* dst = g_hs + (long)(b * CHUNK + row) * (NNODES * HID)
                       + n * HID + c0;
            ((float4*)dst)[0] = v0;
            ((float4*)dst)[1] = v1;
        }
        __syncthreads();                            // dump reads done
        if (tid < HID) hh[0][tid] = hlast;          // carry into next chunk
        __syncthreads();                            // hh[0] visible to all
    }

    // hn / cn (final h is in hh[0] after the last carry)
    if (gate == 0) {
        const int base = 2 * T_SEQ * NNODES;
        out[base + n * HID + k] = hh[0][k];
        out[base + NNODES * HID + n * HID + k] = c_reg;
    }
}

// ---------------------------------------------------------------------------
// Kernel 2: head as a timestep-batched GEMM. 256 CTAs x 16 timesteps each.
// Phase 1: streaming node-mean (float4, unroll-capped), one warp per t.
// Phase 2: thread = column j; ONE weight load per 16 FMAs (acc[16] tile).
// Phase 3: thread = (a, matrix, t-half); one load per 8 FMAs.
// GAT collapses to identity-attention; mean-pool commutes with W_gat.
// ---------------------------------------------------------------------------
__global__ void __launch_bounds__(256, 2)
head_kernel(const float* __restrict__ b_gat,
            const float* __restrict__ b_mean,
            const float* __restrict__ b_std,
            float* __restrict__ out)
{
    const int t0   = blockIdx.x * TB;
    const int tid  = threadIdx.x;
    const int w    = tid >> 5;
    const int lane = tid & 31;

    __shared__ __align__(16) float hb[TB][HID];     // 4 KB
    __shared__ __align__(16) float gs[TB][GATES];   // 16 KB

    // Phase 1: hbar[tt][k] = mean_n h[t0+tt][n][k]; one warp per t, 2 passes
#pragma unroll
    for (int pass = 0; pass < 2; pass++) {
        const int tt = pass * 8 + w;
        const float4* p4 =
            (const float4*)(g_hs + (long)(t0 + tt) * (NNODES * HID));
        const int q  = lane & 15;       // float4 index within a node row
        const int nh = lane >> 4;       // node half
        float4 a = make_float4(0.f, 0.f, 0.f, 0.f);
#pragma unroll 4
        for (int nn = 0; nn < 32; nn++) {
            float4 v = p4[(nh * 32 + nn) * 16 + q];
            a.x += v.x; a.y += v.y; a.z += v.z; a.w += v.w;
        }
        a.x += __shfl_xor_sync(FULLMASK, a.x, 16);
        a.y += __shfl_xor_sync(FULLMASK, a.y, 16);
        a.z += __shfl_xor_sync(FULLMASK, a.z, 16);
        a.w += __shfl_xor_sync(FULLMASK, a.w, 16);
        if (lane < 16) {
            float4 r = make_float4(a.x * (1.0f/64.0f), a.y * (1.0f/64.0f),
                                   a.z * (1.0f/64.0f), a.w * (1.0f/64.0f));
            *(float4*)&hb[tt][4 * q] = r;
        }
    }
    __syncthreads();

    // Phase 2: gs[tt][j] = relu(W_gat[j,:]·hbar[tt] + b_gat[j]); thread = j
    {
        const int j = tid;
        float acc[TB];
#pragma unroll
        for (int tt = 0; tt < TB; tt++) acc[tt] = 0.0f;
#pragma unroll 4
        for (int k = 0; k < HID; k++) {
            const float wv = g_Wg_t[k * GATES + j];
#pragma unroll
            for (int tt = 0; tt < TB; tt++)
                acc[tt] = fmaf(wv, hb[tt][k], acc[tt]);
        }
        const float bg = b_gat[j];
#pragma unroll
        for (int tt = 0; tt < TB; tt++)
            gs[tt][j] = fmaxf(acc[tt] + bg, 0.0f);
    }
    __syncthreads();

    // Phase 3: mean/std heads; thread = (a = tid&63, sel = tid>>6)
    // sel: bit0 = matrix (0 mean, 1 std), bit1 = t-half (0: tt 0-7, 1: 8-15)
    {
        const int a   = tid & 63;
        const int sel = tid >> 6;
        const int mat = sel & 1;
        const int th  = sel >> 1;
        const float* Wt = mat ? g_Ws_t : g_Wm_t;
        float acc[8];
#pragma unroll
        for (int i = 0; i < 8; i++) acc[i] = 0.0f;
#pragma unroll 4
        for (int j = 0; j < GATES; j++) {
            const float wv = Wt[j * HID + a];
#pragma unroll
            for (int i = 0; i < 8; i++)
                acc[i] = fmaf(wv, gs[th * 8 + i][j], acc[i]);
        }
        if (mat == 0) {
            const float bm = b_mean[a];
#pragma unroll
            for (int i = 0; i < 8; i++)
                out[(t0 + th * 8 + i) * NNODES + a] = acc[i] + bm;
        } else {
            const float bs = b_std[a];
#pragma unroll
            for (int i = 0; i < 8; i++) {
                float as = acc[i] + bs;
                float sp = (as > 20.0f) ? as : log1pf(__expf(as));
                sp = fminf(fmaxf(sp, 0.001f), 10.0f);
                out[T_SEQ * NNODES + (t0 + th * 8 + i) * NNODES + a] = sp;
            }
        }
    }
}

// ---------------------------------------------------------------------------
// launch — exactly TWO kernels
// ---------------------------------------------------------------------------
extern "C" void kernel_launch(void* const* d_in, const int* in_sizes, int n_in,
                              void* d_out, int out_size)
{
    const float* x      = (const float*)d_in[0];
    const float* W_ih   = (const float*)d_in[1];
    const float* W_hh   = (const float*)d_in[2];
    const float* b_ih   = (const float*)d_in[3];
    const float* b_hh   = (const float*)d_in[4];
    const float* W_gat  = (const float*)d_in[5];
    // d_in[6], d_in[7] (att_src/att_dst) provably unused: identity adjacency
    // -> softmax over a single unmasked element == 1 for any logits.
    const float* b_gat  = (const float*)d_in[8];
    const float* W_mean = (const float*)d_in[9];
    const float* b_mean = (const float*)d_in[10];
    const float* W_std  = (const float*)d_in[11];
    const float* b_std  = (const float*)d_in[12];
    float* out = (float*)d_out;

    lstm_kernel<<<NNODES + 64, 256>>>(x, W_ih, W_hh, b_ih, b_hh,
                                      W_gat, W_mean, W_std, out);
    head_kernel<<<T_SEQ / TB, 256>>>(b_gat, b_mean, b_std, out);
}